// round 13
// baseline (speedup 1.0000x reference)
#include <cuda_runtime.h>

// Brain connectomic GCN: 2048 independent graphs x 100 nodes x 2000 edges.
// One CTA per graph, 512 threads (16 warps), 2 CTAs/SM (32 warps/SM).
// Each warp owns 6-7 rows -> phase critical paths halved vs 8-warp layout.
// Edges counting-sorted by dst (rank from counting-atomic return; scatter has
// no atomics), hemi edges first per bucket, segments padded even (<=1 pad
// slot, zeroed by the bucket's P4 thread) so aggregation reads edge PAIRS via
// one 8B broadcast. Norm packed: fp32 with src in low 7 mantissa bits
// (<=1.5e-5 perturbation; tolerance 1e-3).

#define NPG 100
#define EPG 2000
#define EMAX 2208
#define NW   16

// ---- shared memory layout (bytes) ----
#define OFF_SH    0        // 6400 f : pre-agg h; later p2@0 / h2@2000 / p3@4000
#define OFF_SH1   25600    // 6400 f : h1
#define OFF_SEA   51200    // 2208 i32 : pk in sort; packed{nrm1,src} in hemi slots
#define OFF_SEB   60032    // 2208 i32 : w in sort; packed{nrm3,src} after
#define OFF_SB    68864    // 192 f : b1l[0..63] b1r[64..127] b2l@128 b2r@148 bg@168
#define OFF_CNT   69632    // 100 i32 packed: hemi count lo16 | cross count hi16
#define OFF_START 70032    // 101 i32 (+pad)
#define OFF_HEND  70448    // 100 i32 (padded hemi end = cross base)
#define OFF_DI1   70848    // 100 f
#define OFF_DI3   71248    // 100 f
#define OFF_PART  71648    // 320 f (16 warps x 20)
#define SMEM_TOTAL 72928

__device__ __forceinline__ float lrelu(float v) {
    return v > 0.f ? v : 0.01f * v;
}
__device__ __forceinline__ int pack_ns(float nrm, int src) {
    return (__float_as_int(nrm) & ~0x7F) | src;
}
__device__ __forceinline__ unsigned long long pk2(float a, float b) {
    unsigned long long r;
    asm("mov.b64 %0,{%1,%2};" : "=l"(r) : "f"(a), "f"(b));
    return r;
}
#define FMA2(acc, a, b) asm("fma.rn.f32x2 %0,%1,%2,%0;" : "+l"(acc) : "l"(a), "l"(b))

extern __shared__ char S[];

__global__ void __launch_bounds__(512, 2) gcn_fused_kernel(
    const float* __restrict__ x,   const float* __restrict__ ea,
    const float* __restrict__ Wl1, const float* __restrict__ bl1,
    const float* __restrict__ Wr1, const float* __restrict__ br1,
    const float* __restrict__ Wl2, const float* __restrict__ bl2,
    const float* __restrict__ Wr2, const float* __restrict__ br2,
    const float* __restrict__ Wg,  const float* __restrict__ bg,
    const int* __restrict__ eidx, long long Etot,
    float* __restrict__ out)
{
    float* sh   = (float*)(S + OFF_SH);
    float* sh1  = (float*)(S + OFF_SH1);
    int*   seA  = (int*)  (S + OFF_SEA);
    int*   seB  = (int*)  (S + OFF_SEB);
    float* sb   = (float*)(S + OFF_SB);
    int*   scnt = (int*)  (S + OFF_CNT);
    int*   sstart=(int*)  (S + OFF_START);
    int*   shend= (int*)  (S + OFF_HEND);
    float* sdi1 = (float*)(S + OFF_DI1);
    float* sdi3 = (float*)(S + OFF_DI3);
    float* spart= (float*)(S + OFF_PART);
    float* p2 = sh;          // 2000 f
    float* h2 = sh + 2000;   // 2000 f
    float* p3 = sh + 4000;   // 2000 f

    const int g    = blockIdx.x;
    const int tid  = threadIdx.x;
    const int w    = tid >> 5;
    const int lane = tid & 31;
    const int hw    = w & 7;
    const int base0 = (w < 8) ? 0 : 50;
    const int nr    = (hw < 2) ? 7 : 6;     // rows d = base0 + hw + 8*t

    // ---------------- P0: biases; zero counters ---------------------------
    if (tid < 64) { sb[tid] = bl1[tid]; sb[64 + tid] = br1[tid]; }
    if (tid < 20) { sb[128 + tid] = bl2[tid]; sb[148 + tid] = br2[tid];
                    sb[168 + tid] = bg[tid]; }
    if (tid < 100) scnt[tid] = 0;
    __syncthreads();

    // ---------------- P1: load edges; count + capture rank ----------------
    int   myPk[4];
    float myW[4];
    {
        const size_t gbase = (size_t)g * EPG;
        const int    noff  = g * NPG;
        #pragma unroll
        for (int r = 0; r < 4; ++r) {
            int e = tid + 512 * r;
            if (e < EPG) {
                int ls = eidx[gbase + e] - noff;
                int ld = eidx[(size_t)Etot + gbase + e] - noff;
                float wv = ea[gbase + e];
                int hemi = ((ls < 50) == (ld < 50)) ? 1 : 0;
                int old = atomicAdd(&scnt[ld], hemi ? 1 : 0x10000);
                int rank = hemi ? (old & 0xffff) : (old >> 16);
                myPk[r] = ls | (ld << 8) | (hemi << 16) | (rank << 17);
                myW[r]  = wv;
            } else {
                myPk[r] = -1; myW[r] = 0.f;
            }
        }
    }
    __syncthreads();

    // ---------------- P2: prefix sum over even-padded buckets (warp 0) ----
    if (w == 0) {
        int hp[4], cp[4];
        int tot = 0;
        #pragma unroll
        for (int i = 0; i < 4; ++i) {
            int b = lane * 4 + i;
            int v = (b < 100) ? scnt[b] : 0;
            hp[i] = ((v & 0xffff) + 1) & ~1;
            cp[i] = ((v >> 16) + 1) & ~1;
            tot += hp[i] + cp[i];
        }
        int incl = tot;
        #pragma unroll
        for (int off = 1; off < 32; off <<= 1) {
            int v = __shfl_up_sync(0xffffffffu, incl, off);
            if (lane >= off) incl += v;
        }
        int run = incl - tot;
        #pragma unroll
        for (int i = 0; i < 4; ++i) {
            int b = lane * 4 + i;
            if (b < 100) {
                sstart[b] = run;
                shend[b]  = run + hp[i];
                run += hp[i] + cp[i];
            }
        }
        if (lane == 31) sstart[100] = run;
    }
    __syncthreads();

    // ---------------- P3: scatter (no atomics: pos = base + rank) ---------
    #pragma unroll
    for (int r = 0; r < 4; ++r) {
        int pk = myPk[r];
        if (pk >= 0) {
            int ld   = (pk >> 8) & 0xff;
            int rank = (pk >> 17) & 0x7ff;
            int pos  = ((pk & (1 << 16)) ? sstart[ld] : shend[ld]) + rank;
            seA[pos] = pk;
            seB[pos] = __float_as_int(myW[r]);
        }
    }
    __syncthreads();

    // ---------------- P4: zero pad slots; degrees -> dinv -----------------
    if (tid < 100) {
        int s = sstart[tid], he = shend[tid], e1 = sstart[tid + 1];
        int v  = scnt[tid];
        int hc = v & 0xffff, cc = v >> 16;
        if (hc & 1) { seA[s + hc] = 0; seB[s + hc] = 0; }       // hemi pad
        if (cc & 1) { seA[he + cc] = 0; seB[he + cc] = 0; }     // cross pad
        float dg1 = 1.f, dg3 = 1.f;
        for (int e = s; e < e1; ++e) {
            float wv = __int_as_float(seB[e]);
            dg3 += wv;
            if (e < he) dg1 += wv;
        }
        sdi1[tid] = rsqrtf(dg1);
        sdi3[tid] = rsqrtf(dg3);
    }
    __syncthreads();

    // ---------------- P5: per-edge norm precompute (packed 4B) ------------
    {
        const int total = sstart[100];
        #pragma unroll
        for (int r = 0; r < 5; ++r) {
            int e = tid + 512 * r;
            if (e < total) {
                int pk = seA[e];
                float wv = __int_as_float(seB[e]);
                int ls = pk & 0xff;
                int ld = (pk >> 8) & 0xff;
                seB[e] = pack_ns(sdi3[ls] * wv * sdi3[ld], ls);
                if (pk & (1 << 16))
                    seA[e] = pack_ns(sdi1[ls] * wv * sdi1[ld], ls);
            }
        }
    }
    __syncthreads();

    // ---------------- P6: GEMM1  sh = x @ W(hemi)  [100,64] ---------------
    // Lane owns cols (lane, lane+32); single pass over <=7 rows; W loaded
    // once per k-quad; x read as k-quad LDG.128 (warp-uniform broadcast).
    {
        const float* Wb = (w < 8) ? Wl1 : Wr1;
        const float* xg = x + (size_t)g * NPG * 100;
        unsigned long long accA[7], accB[7];
        #pragma unroll
        for (int r = 0; r < 7; ++r) { accA[r] = 0ull; accB[r] = 0ull; }
        for (int k = 0; k < 100; k += 4) {
            float wa0 = __ldg(Wb + (k + 0) * 64 + lane);
            float wa1 = __ldg(Wb + (k + 1) * 64 + lane);
            float wa2 = __ldg(Wb + (k + 2) * 64 + lane);
            float wa3 = __ldg(Wb + (k + 3) * 64 + lane);
            float wb0 = __ldg(Wb + (k + 0) * 64 + lane + 32);
            float wb1 = __ldg(Wb + (k + 1) * 64 + lane + 32);
            float wb2 = __ldg(Wb + (k + 2) * 64 + lane + 32);
            float wb3 = __ldg(Wb + (k + 3) * 64 + lane + 32);
            unsigned long long wA01 = pk2(wa0, wa1);
            unsigned long long wA23 = pk2(wa2, wa3);
            unsigned long long wB01 = pk2(wb0, wb1);
            unsigned long long wB23 = pk2(wb2, wb3);
            #pragma unroll
            for (int r = 0; r < 7; ++r) {
                if (r < nr) {
                    int d = base0 + hw + 8 * r;
                    ulonglong2 xq = __ldg((const ulonglong2*)(xg + d * 100 + k));
                    FMA2(accA[r], xq.x, wA01);
                    FMA2(accA[r], xq.y, wA23);
                    FMA2(accB[r], xq.x, wB01);
                    FMA2(accB[r], xq.y, wB23);
                }
            }
        }
        #pragma unroll
        for (int r = 0; r < 7; ++r) {
            if (r < nr) {
                int d = base0 + hw + 8 * r;
                float2 a = *(float2*)&accA[r];
                float2 b = *(float2*)&accB[r];
                sh[d * 64 + lane]      = a.x + a.y;
                sh[d * 64 + lane + 32] = b.x + b.y;
            }
        }
    }
    __syncthreads();

    // ---------------- P7: aggregate layer1 -> h1 (hemi, edge PAIRS) -------
    for (int t = 0; t < nr; ++t) {
        int d = base0 + hw + 8 * t;
        float dv = sdi1[d];
        float self = dv * dv;
        float a0 = sh[d * 64 + lane] * self;
        float a1 = sh[d * 64 + lane + 32] * self;
        int e0 = sstart[d], e1 = shend[d];        // both even
        for (int e = e0; e < e1; e += 2) {
            int2 b2 = *(const int2*)&seA[e];      // 8B broadcast: 2 packed edges
            int   ls0 = (b2.x & 0x7F) << 6;
            float nm0 = __int_as_float(b2.x & ~0x7F);
            int   ls1 = (b2.y & 0x7F) << 6;
            float nm1 = __int_as_float(b2.y & ~0x7F);
            a0 = fmaf(sh[ls0 + lane],      nm0, a0);
            a1 = fmaf(sh[ls0 + lane + 32], nm0, a1);
            a0 = fmaf(sh[ls1 + lane],      nm1, a0);
            a1 = fmaf(sh[ls1 + lane + 32], nm1, a1);
        }
        int bb = (d < 50) ? 0 : 64;
        sh1[d * 64 + lane]      = lrelu(a0 + sb[bb + lane]);
        sh1[d * 64 + lane + 32] = lrelu(a1 + sb[bb + lane + 32]);
    }
    __syncthreads();

    // ---------------- P8: GEMM2  p2 = h1 @ W2(hemi)  [100,20] -------------
    if (lane < 20) {
        const float* W2 = (w < 8) ? Wl2 : Wr2;
        float acc[7];
        #pragma unroll
        for (int r = 0; r < 7; ++r) acc[r] = 0.f;
        for (int kc = 0; kc < 64; kc += 16) {
            float wreg[16];
            #pragma unroll
            for (int i = 0; i < 16; ++i) wreg[i] = __ldg(W2 + (kc + i) * 20 + lane);
            for (int t = 0; t < nr; ++t) {
                int d = base0 + hw + 8 * t;
                const float* hr = sh1 + d * 64 + kc;
                #pragma unroll
                for (int i = 0; i < 16; i += 4) {
                    float4 hv = *(const float4*)(hr + i);
                    acc[t] = fmaf(hv.x, wreg[i + 0], acc[t]);
                    acc[t] = fmaf(hv.y, wreg[i + 1], acc[t]);
                    acc[t] = fmaf(hv.z, wreg[i + 2], acc[t]);
                    acc[t] = fmaf(hv.w, wreg[i + 3], acc[t]);
                }
            }
        }
        for (int t = 0; t < nr; ++t) {
            int d = base0 + hw + 8 * t;
            p2[d * 20 + lane] = acc[t];
        }
    }
    __syncthreads();

    // ---------------- P9: aggregate layer2 -> h2 (hemi, edge PAIRS) -------
    if (lane < 20) {
        for (int t = 0; t < nr; ++t) {
            int d = base0 + hw + 8 * t;
            float dv = sdi1[d];
            float a = p2[d * 20 + lane] * dv * dv;
            int e0 = sstart[d], e1 = shend[d];
            for (int e = e0; e < e1; e += 2) {
                int2 b2 = *(const int2*)&seA[e];
                a = fmaf(p2[(b2.x & 0x7F) * 20 + lane], __int_as_float(b2.x & ~0x7F), a);
                a = fmaf(p2[(b2.y & 0x7F) * 20 + lane], __int_as_float(b2.y & ~0x7F), a);
            }
            int bb = (d < 50) ? 128 : 148;
            h2[d * 20 + lane] = lrelu(a + sb[bb + lane]);
        }
    }
    __syncthreads();

    // ---------------- P10: GEMM3  p3 = h2 @ Wg  [100,20] ------------------
    if (lane < 20) {
        float wg[20];
        #pragma unroll
        for (int k = 0; k < 20; ++k) wg[k] = __ldg(Wg + k * 20 + lane);
        for (int t = 0; t < nr; ++t) {
            int d = base0 + hw + 8 * t;
            float acc = 0.f;
            #pragma unroll
            for (int k = 0; k < 20; ++k)
                acc = fmaf(h2[d * 20 + k], wg[k], acc);
            p3[d * 20 + lane] = acc;
        }
    }
    __syncthreads();

    // ---------------- P11: aggregate layer3 (all edges, PAIRS) + pool -----
    {
        float pool = 0.f;
        if (lane < 20) {
            for (int t = 0; t < nr; ++t) {
                int d = base0 + hw + 8 * t;
                float dv = sdi3[d];
                float a = p3[d * 20 + lane] * dv * dv;
                int e0 = sstart[d], e1 = sstart[d + 1];
                for (int e = e0; e < e1; e += 2) {
                    int2 b2 = *(const int2*)&seB[e];
                    a = fmaf(p3[(b2.x & 0x7F) * 20 + lane], __int_as_float(b2.x & ~0x7F), a);
                    a = fmaf(p3[(b2.y & 0x7F) * 20 + lane], __int_as_float(b2.y & ~0x7F), a);
                }
                pool += lrelu(a + sb[168 + lane]);
            }
            spart[w * 20 + lane] = pool;
        }
    }
    __syncthreads();

    if (tid < 20) {
        float s = 0.f;
        #pragma unroll
        for (int ww = 0; ww < NW; ++ww) s += spart[ww * 20 + tid];
        out[(size_t)g * 20 + tid] = s * 0.01f;
    }
}

extern "C" void kernel_launch(void* const* d_in, const int* in_sizes, int n_in,
                              void* d_out, int out_size)
{
    (void)n_in;
    const long long Etot = (long long)in_sizes[1];
    const int numGraphs = (int)(Etot / EPG);

    cudaFuncSetAttribute(gcn_fused_kernel,
                         cudaFuncAttributeMaxDynamicSharedMemorySize, SMEM_TOTAL);

    gcn_fused_kernel<<<numGraphs, 512, SMEM_TOTAL>>>(
        (const float*)d_in[0],  (const float*)d_in[1],
        (const float*)d_in[2],  (const float*)d_in[3],
        (const float*)d_in[4],  (const float*)d_in[5],
        (const float*)d_in[6],  (const float*)d_in[7],
        (const float*)d_in[8],  (const float*)d_in[9],
        (const float*)d_in[10], (const float*)d_in[11],
        (const int*)d_in[12], Etot,
        (float*)d_out);
    (void)out_size;
}

// round 15
// speedup vs baseline: 1.1744x; 1.1744x over previous
#include <cuda_runtime.h>

// Brain connectomic GCN: 2048 independent graphs x 100 nodes x 2000 edges.
// One CTA per graph (grid=2048), 256 threads, 4 CTAs/SM (32 warps/SM with
// 8-warp barrier scope). Edges counting-sorted by dst (rank from the
// counting-atomic return; no scatter atomics), hemi edges first per bucket,
// segments padded even so aggregation reads edge PAIRS via one 8B broadcast.
// Norm packed: fp32 with src in low 7 mantissa bits (<=1.5e-5 perturbation).
// smem diet: h1 and p2 are staged in REGISTERS and written back into the
// pre-agg buffer after a barrier (its data is dead) -> no sh1 buffer,
// 46.7KB smem -> 4 CTAs/SM.

#define NPG 100
#define EPG 2000
#define EMAX 2208

// ---- shared memory layout (bytes), total 46688 <= 48KB alloc ----
#define OFF_SH    0        // 6400 f : pre-agg h; then h1; p2@0 / h2@2000 / p3@4000
#define OFF_SEA   25600    // 2208 i32 : pk in sort; packed{nrm1,src} in hemi slots
#define OFF_SEB   34432    // 2208 i32 : w in sort; packed{nrm3,src} after
#define OFF_SB    43264    // 192 f : b1l[0..63] b1r[64..127] b2l@128 b2r@148 bg@168
#define OFF_CNT   44032    // 100 i32 packed: hemi count lo16 | cross count hi16
#define OFF_START 44432    // 101 i32 (+pad)
#define OFF_HEND  44848    // 100 i32 (padded hemi end = cross base)
#define OFF_DI1   45248    // 100 f
#define OFF_DI3   45648    // 100 f
#define OFF_PART  46048    // 160 f (8 warps x 20)
#define SMEM_TOTAL 46688

__device__ __forceinline__ float lrelu(float v) {
    return v > 0.f ? v : 0.01f * v;
}
__device__ __forceinline__ int pack_ns(float nrm, int src) {
    return (__float_as_int(nrm) & ~0x7F) | src;
}
__device__ __forceinline__ unsigned long long pk2(float a, float b) {
    unsigned long long r;
    asm("mov.b64 %0,{%1,%2};" : "=l"(r) : "f"(a), "f"(b));
    return r;
}
#define FMA2(acc, a, b) asm("fma.rn.f32x2 %0,%1,%2,%0;" : "+l"(acc) : "l"(a), "l"(b))

extern __shared__ char S[];

__global__ void __launch_bounds__(256, 4) gcn_fused_kernel(
    const float* __restrict__ x,   const float* __restrict__ ea,
    const float* __restrict__ Wl1, const float* __restrict__ bl1,
    const float* __restrict__ Wr1, const float* __restrict__ br1,
    const float* __restrict__ Wl2, const float* __restrict__ bl2,
    const float* __restrict__ Wr2, const float* __restrict__ br2,
    const float* __restrict__ Wg,  const float* __restrict__ bg,
    const int* __restrict__ eidx, long long Etot,
    float* __restrict__ out)
{
    float* sh   = (float*)(S + OFF_SH);
    int*   seA  = (int*)  (S + OFF_SEA);
    int*   seB  = (int*)  (S + OFF_SEB);
    float* sb   = (float*)(S + OFF_SB);
    int*   scnt = (int*)  (S + OFF_CNT);
    int*   sstart=(int*)  (S + OFF_START);
    int*   shend= (int*)  (S + OFF_HEND);
    float* sdi1 = (float*)(S + OFF_DI1);
    float* sdi3 = (float*)(S + OFF_DI3);
    float* spart= (float*)(S + OFF_PART);
    float* p2 = sh;          // 2000 f (after h1 dead)
    float* h2 = sh + 2000;   // 2000 f
    float* p3 = sh + 4000;   // 2000 f

    const int g    = blockIdx.x;
    const int tid  = threadIdx.x;
    const int w    = tid >> 5;
    const int lane = tid & 31;
    const int hw    = w & 3;
    const int base0 = (w < 4) ? 0 : 50;
    const int nr    = (hw < 2) ? 13 : 12;   // rows d = base0 + hw + 4*t

    // ---------------- P0: biases; zero counters ---------------------------
    if (tid < 64) { sb[tid] = bl1[tid]; sb[64 + tid] = br1[tid]; }
    if (tid < 20) { sb[128 + tid] = bl2[tid]; sb[148 + tid] = br2[tid];
                    sb[168 + tid] = bg[tid]; }
    if (tid < 100) scnt[tid] = 0;
    __syncthreads();

    // ---------------- P1: load edges; count + capture rank ----------------
    int   myPk[8];
    float myW[8];
    {
        const size_t gbase = (size_t)g * EPG;
        const int    noff  = g * NPG;
        #pragma unroll
        for (int r = 0; r < 8; ++r) {
            int e = tid + 256 * r;
            if (e < EPG) {
                int ls = eidx[gbase + e] - noff;
                int ld = eidx[(size_t)Etot + gbase + e] - noff;
                float wv = ea[gbase + e];
                int hemi = ((ls < 50) == (ld < 50)) ? 1 : 0;
                int old = atomicAdd(&scnt[ld], hemi ? 1 : 0x10000);
                int rank = hemi ? (old & 0xffff) : (old >> 16);
                myPk[r] = ls | (ld << 8) | (hemi << 16) | (rank << 17);
                myW[r]  = wv;
            } else {
                myPk[r] = -1; myW[r] = 0.f;
            }
        }
    }
    __syncthreads();

    // ---------------- P2: prefix sum over even-padded buckets (warp 0) ----
    if (w == 0) {
        int hp[4], cp[4];
        int tot = 0;
        #pragma unroll
        for (int i = 0; i < 4; ++i) {
            int b = lane * 4 + i;
            int v = (b < 100) ? scnt[b] : 0;
            hp[i] = ((v & 0xffff) + 1) & ~1;
            cp[i] = ((v >> 16) + 1) & ~1;
            tot += hp[i] + cp[i];
        }
        int incl = tot;
        #pragma unroll
        for (int off = 1; off < 32; off <<= 1) {
            int v = __shfl_up_sync(0xffffffffu, incl, off);
            if (lane >= off) incl += v;
        }
        int run = incl - tot;
        #pragma unroll
        for (int i = 0; i < 4; ++i) {
            int b = lane * 4 + i;
            if (b < 100) {
                sstart[b] = run;
                shend[b]  = run + hp[i];
                run += hp[i] + cp[i];
            }
        }
        if (lane == 31) sstart[100] = run;
    }
    __syncthreads();

    // ---------------- P3: scatter (no atomics: pos = base + rank) ---------
    #pragma unroll
    for (int r = 0; r < 8; ++r) {
        int pk = myPk[r];
        if (pk >= 0) {
            int ld   = (pk >> 8) & 0xff;
            int rank = (pk >> 17) & 0x7ff;
            int pos  = ((pk & (1 << 16)) ? sstart[ld] : shend[ld]) + rank;
            seA[pos] = pk;
            seB[pos] = __float_as_int(myW[r]);
        }
    }
    __syncthreads();

    // ---------------- P4: zero pad slots; degrees -> dinv -----------------
    if (tid < 100) {
        int s = sstart[tid], he = shend[tid], e1 = sstart[tid + 1];
        int v  = scnt[tid];
        int hc = v & 0xffff, cc = v >> 16;
        if (hc & 1) { seA[s + hc] = 0; seB[s + hc] = 0; }       // hemi pad
        if (cc & 1) { seA[he + cc] = 0; seB[he + cc] = 0; }     // cross pad
        float dg1 = 1.f, dg3 = 1.f;
        for (int e = s; e < e1; ++e) {
            float wv = __int_as_float(seB[e]);
            dg3 += wv;
            if (e < he) dg1 += wv;
        }
        sdi1[tid] = rsqrtf(dg1);
        sdi3[tid] = rsqrtf(dg3);
    }
    __syncthreads();

    // ---------------- P5: per-edge norm precompute (packed 4B) ------------
    {
        const int total = sstart[100];
        #pragma unroll
        for (int r = 0; r < 9; ++r) {
            int e = tid + 256 * r;
            if (e < total) {
                int pk = seA[e];
                float wv = __int_as_float(seB[e]);
                int ls = pk & 0xff;
                int ld = (pk >> 8) & 0xff;
                seB[e] = pack_ns(sdi3[ls] * wv * sdi3[ld], ls);
                if (pk & (1 << 16))
                    seA[e] = pack_ns(sdi1[ls] * wv * sdi1[ld], ls);
            }
        }
    }
    __syncthreads();

    // ---------------- P6: GEMM1  sh = x @ W(hemi)  [100,64] ---------------
    // 3 row-groups (5/4/4) to fit 64-reg cap at 4 CTAs/SM; x read as k-quad
    // LDG.128 (warp-uniform broadcast); f32x2 accumulate.
    {
        const float* Wb = (w < 4) ? Wl1 : Wr1;
        const float* xg = x + (size_t)g * NPG * 100;
        #pragma unroll
        for (int grp = 0; grp < 3; ++grp) {
            const int t0 = (grp == 0) ? 0 : (grp == 1 ? 5 : 9);
            const int gsz = (grp == 0) ? 5 : 4;
            const int tcnt = (t0 + gsz <= nr) ? gsz : (nr - t0);
            unsigned long long accA[5], accB[5];
            #pragma unroll
            for (int r = 0; r < 5; ++r) { accA[r] = 0ull; accB[r] = 0ull; }
            for (int k = 0; k < 100; k += 4) {
                float wa0 = __ldg(Wb + (k + 0) * 64 + lane);
                float wa1 = __ldg(Wb + (k + 1) * 64 + lane);
                float wa2 = __ldg(Wb + (k + 2) * 64 + lane);
                float wa3 = __ldg(Wb + (k + 3) * 64 + lane);
                float wb0 = __ldg(Wb + (k + 0) * 64 + lane + 32);
                float wb1 = __ldg(Wb + (k + 1) * 64 + lane + 32);
                float wb2 = __ldg(Wb + (k + 2) * 64 + lane + 32);
                float wb3 = __ldg(Wb + (k + 3) * 64 + lane + 32);
                unsigned long long wA01 = pk2(wa0, wa1);
                unsigned long long wA23 = pk2(wa2, wa3);
                unsigned long long wB01 = pk2(wb0, wb1);
                unsigned long long wB23 = pk2(wb2, wb3);
                #pragma unroll
                for (int r = 0; r < 5; ++r) {
                    if (r < tcnt) {
                        int d = base0 + hw + 4 * (t0 + r);
                        ulonglong2 xq =
                            __ldg((const ulonglong2*)(xg + d * 100 + k));
                        FMA2(accA[r], xq.x, wA01);
                        FMA2(accA[r], xq.y, wA23);
                        FMA2(accB[r], xq.x, wB01);
                        FMA2(accB[r], xq.y, wB23);
                    }
                }
            }
            #pragma unroll
            for (int r = 0; r < 5; ++r) {
                if (r < tcnt) {
                    int d = base0 + hw + 4 * (t0 + r);
                    float2 a = *(float2*)&accA[r];
                    float2 b = *(float2*)&accB[r];
                    sh[d * 64 + lane]      = a.x + a.y;
                    sh[d * 64 + lane + 32] = b.x + b.y;
                }
            }
        }
    }
    __syncthreads();

    // ---------------- P7: aggregate layer1 -> h1 in REGS; write into sh ---
    {
        float h1a[13], h1b[13];
        for (int t = 0; t < nr; ++t) {
            int d = base0 + hw + 4 * t;
            float dv = sdi1[d];
            float self = dv * dv;
            float a0 = sh[d * 64 + lane] * self;
            float a1 = sh[d * 64 + lane + 32] * self;
            int e0 = sstart[d], e1 = shend[d];    // both even
            for (int e = e0; e < e1; e += 2) {
                int2 b2 = *(const int2*)&seA[e];  // 8B broadcast: 2 edges
                int   ls0 = (b2.x & 0x7F) << 6;
                float nm0 = __int_as_float(b2.x & ~0x7F);
                int   ls1 = (b2.y & 0x7F) << 6;
                float nm1 = __int_as_float(b2.y & ~0x7F);
                a0 = fmaf(sh[ls0 + lane],      nm0, a0);
                a1 = fmaf(sh[ls0 + lane + 32], nm0, a1);
                a0 = fmaf(sh[ls1 + lane],      nm1, a0);
                a1 = fmaf(sh[ls1 + lane + 32], nm1, a1);
            }
            int bb = (d < 50) ? 0 : 64;
            h1a[t] = lrelu(a0 + sb[bb + lane]);
            h1b[t] = lrelu(a1 + sb[bb + lane + 32]);
        }
        __syncthreads();          // all pre-agg reads complete
        for (int t = 0; t < nr; ++t) {
            int d = base0 + hw + 4 * t;
            sh[d * 64 + lane]      = h1a[t];
            sh[d * 64 + lane + 32] = h1b[t];
        }
    }
    __syncthreads();

    // ---------------- P8: GEMM2  p2 = h1 @ W2(hemi) in REGS; write to sh --
    {
        float acc[13];
        if (lane < 20) {
            const float* W2 = (w < 4) ? Wl2 : Wr2;
            #pragma unroll
            for (int r = 0; r < 13; ++r) acc[r] = 0.f;
            for (int kc = 0; kc < 64; kc += 16) {
                float wreg[16];
                #pragma unroll
                for (int i = 0; i < 16; ++i)
                    wreg[i] = __ldg(W2 + (kc + i) * 20 + lane);
                for (int t = 0; t < nr; ++t) {
                    int d = base0 + hw + 4 * t;
                    const float* hr = sh + d * 64 + kc;
                    #pragma unroll
                    for (int i = 0; i < 16; i += 4) {
                        float4 hv = *(const float4*)(hr + i);
                        acc[t] = fmaf(hv.x, wreg[i + 0], acc[t]);
                        acc[t] = fmaf(hv.y, wreg[i + 1], acc[t]);
                        acc[t] = fmaf(hv.z, wreg[i + 2], acc[t]);
                        acc[t] = fmaf(hv.w, wreg[i + 3], acc[t]);
                    }
                }
            }
        }
        __syncthreads();          // all h1 reads complete
        if (lane < 20) {
            for (int t = 0; t < nr; ++t) {
                int d = base0 + hw + 4 * t;
                p2[d * 20 + lane] = acc[t];
            }
        }
    }
    __syncthreads();

    // ---------------- P9: aggregate layer2 -> h2 (hemi, edge PAIRS) -------
    if (lane < 20) {
        for (int t = 0; t < nr; ++t) {
            int d = base0 + hw + 4 * t;
            float dv = sdi1[d];
            float a = p2[d * 20 + lane] * dv * dv;
            int e0 = sstart[d], e1 = shend[d];
            for (int e = e0; e < e1; e += 2) {
                int2 b2 = *(const int2*)&seA[e];
                a = fmaf(p2[(b2.x & 0x7F) * 20 + lane], __int_as_float(b2.x & ~0x7F), a);
                a = fmaf(p2[(b2.y & 0x7F) * 20 + lane], __int_as_float(b2.y & ~0x7F), a);
            }
            int bb = (d < 50) ? 128 : 148;
            h2[d * 20 + lane] = lrelu(a + sb[bb + lane]);
        }
    }
    __syncthreads();

    // ---------------- P10: GEMM3  p3 = h2 @ Wg  [100,20] ------------------
    if (lane < 20) {
        float wg[20];
        #pragma unroll
        for (int k = 0; k < 20; ++k) wg[k] = __ldg(Wg + k * 20 + lane);
        for (int t = 0; t < nr; ++t) {
            int d = base0 + hw + 4 * t;
            float acc = 0.f;
            #pragma unroll
            for (int k = 0; k < 20; ++k)
                acc = fmaf(h2[d * 20 + k], wg[k], acc);
            p3[d * 20 + lane] = acc;
        }
    }
    __syncthreads();

    // ---------------- P11: aggregate layer3 (all edges, PAIRS) + pool -----
    {
        float pool = 0.f;
        if (lane < 20) {
            for (int t = 0; t < nr; ++t) {
                int d = base0 + hw + 4 * t;
                float dv = sdi3[d];
                float a = p3[d * 20 + lane] * dv * dv;
                int e0 = sstart[d], e1 = sstart[d + 1];
                for (int e = e0; e < e1; e += 2) {
                    int2 b2 = *(const int2*)&seB[e];
                    a = fmaf(p3[(b2.x & 0x7F) * 20 + lane], __int_as_float(b2.x & ~0x7F), a);
                    a = fmaf(p3[(b2.y & 0x7F) * 20 + lane], __int_as_float(b2.y & ~0x7F), a);
                }
                pool += lrelu(a + sb[168 + lane]);
            }
            spart[w * 20 + lane] = pool;
        }
    }
    __syncthreads();

    if (tid < 20) {
        float s = 0.f;
        #pragma unroll
        for (int ww = 0; ww < 8; ++ww) s += spart[ww * 20 + tid];
        out[(size_t)g * 20 + tid] = s * 0.01f;
    }
}

extern "C" void kernel_launch(void* const* d_in, const int* in_sizes, int n_in,
                              void* d_out, int out_size)
{
    (void)n_in;
    const long long Etot = (long long)in_sizes[1];
    const int numGraphs = (int)(Etot / EPG);

    cudaFuncSetAttribute(gcn_fused_kernel,
                         cudaFuncAttributeMaxDynamicSharedMemorySize, SMEM_TOTAL);

    gcn_fused_kernel<<<numGraphs, 256, SMEM_TOTAL>>>(
        (const float*)d_in[0],  (const float*)d_in[1],
        (const float*)d_in[2],  (const float*)d_in[3],
        (const float*)d_in[4],  (const float*)d_in[5],
        (const float*)d_in[6],  (const float*)d_in[7],
        (const float*)d_in[8],  (const float*)d_in[9],
        (const float*)d_in[10], (const float*)d_in[11],
        (const int*)d_in[12], Etot,
        (float*)d_out);
    (void)out_size;
}